// round 1
// baseline (speedup 1.0000x reference)
#include <cuda_runtime.h>
#include <cuda_bf16.h>

#define NN 50000
#define EE 1600000
#define ETOT (EE + NN)
#define HD 128

// ---------------- scratch (static device globals; no allocation) ------------
__device__ float g_xl[NN * HD];
__device__ float g_xr[NN * HD];
__device__ int   g_cnt[NN];
__device__ int   g_rowptr[NN + 1];
__device__ int   g_cursor[NN];
__device__ int   g_src[ETOT];

// ---------------- init: counts=1 (self loop), zero pooled output ------------
__global__ void init_kernel(float* __restrict__ out, int n, int out_elems) {
    int i = blockIdx.x * blockDim.x + threadIdx.x;
    if (i < n) g_cnt[i] = 1;                 // self-loop pre-count
    if (i < out_elems) out[i] = 0.0f;        // pooled init (matches isfinite->0 guard)
}

// ---------------- fused dual GEMM: xl = xW_l+b_l, xr = xW_r+b_r -------------
// block: 256 threads, 16 rows of x per block. Thread col 0..127 -> W_l, 128..255 -> W_r
__global__ void gemm_lr_kernel(const float* __restrict__ x,
                               const float* __restrict__ Wl, const float* __restrict__ bl,
                               const float* __restrict__ Wr, const float* __restrict__ br,
                               int n) {
    __shared__ float xs[16][HD];
    int row0 = blockIdx.x * 16;
    for (int i = threadIdx.x; i < 16 * HD; i += 256) {
        int r = i >> 7, c = i & 127;
        int row = row0 + r;
        xs[r][c] = (row < n) ? x[row * HD + c] : 0.0f;
    }
    __syncthreads();

    int col = threadIdx.x;
    const float* W = (col < HD) ? Wl : Wr;
    int c = col & 127;
    float bias = (col < HD) ? bl[c] : br[c];
    float acc[16];
#pragma unroll
    for (int r = 0; r < 16; r++) acc[r] = bias;

    for (int k = 0; k < HD; k++) {
        float w = W[k * HD + c];
#pragma unroll
        for (int r = 0; r < 16; r++) acc[r] = fmaf(xs[r][k], w, acc[r]);
    }
    float* dstbuf = (col < HD) ? g_xl : g_xr;
#pragma unroll
    for (int r = 0; r < 16; r++) {
        int row = row0 + r;
        if (row < n) dstbuf[row * HD + c] = acc[r];
    }
}

// ---------------- CSR build: count -> scan -> fill --------------------------
__global__ void count_kernel(const int* __restrict__ dst, int E) {
    int i = blockIdx.x * blockDim.x + threadIdx.x;
    if (i < E) atomicAdd(&g_cnt[dst[i]], 1);
}

// single block of 1024 threads; each thread owns a contiguous chunk
__global__ void scan_kernel(int n) {
    __shared__ int ssum[1024];
    int chunk = (n + 1023) / 1024;
    int beg = threadIdx.x * chunk;
    int end = min(beg + chunk, n);
    int s = 0;
    for (int i = beg; i < end; i++) s += g_cnt[i];
    ssum[threadIdx.x] = s;
    __syncthreads();
    // inclusive Hillis-Steele scan
    for (int off = 1; off < 1024; off <<= 1) {
        int t = 0;
        if ((int)threadIdx.x >= off) t = ssum[threadIdx.x - off];
        __syncthreads();
        ssum[threadIdx.x] += t;
        __syncthreads();
    }
    int run = ssum[threadIdx.x] - s;  // exclusive base for this thread
    for (int i = beg; i < end; i++) {
        int cval = g_cnt[i];
        g_rowptr[i] = run;
        g_cursor[i] = run;
        run += cval;
    }
    if (threadIdx.x == 1023) g_rowptr[n] = ssum[1023];
}

__global__ void fill_kernel(const int* __restrict__ src, const int* __restrict__ dst,
                            int E, int n) {
    int i = blockIdx.x * blockDim.x + threadIdx.x;
    if (i < E + n) {
        int s, d;
        if (i < E) { s = src[i]; d = dst[i]; }
        else       { s = i - E; d = s; }       // self loop
        int pos = atomicAdd(&g_cursor[d], 1);
        g_src[pos] = s;
    }
}

// ---------------- main fused GATv2 kernel: one warp per dst node ------------
// logits + softmax (shift-free) + weighted aggregation + bias + relu + pooled max
__device__ __forceinline__ float lrelu(float v) {
    return (v > 0.0f) ? v : 0.2f * v;
}

__global__ void gat_main_kernel(const float* __restrict__ att,
                                const float* __restrict__ bias,
                                const int* __restrict__ batch,
                                float* __restrict__ pooled, int n) {
    int gw = (blockIdx.x * blockDim.x + threadIdx.x) >> 5;
    int lane = threadIdx.x & 31;
    if (gw >= n) return;
    int i = gw;

    // lane l owns channels [4l, 4l+4); head h = l>>3; att flat index = 4l
    float4 xr = ((const float4*)g_xr)[i * 32 + lane];
    float4 av = ((const float4*)att)[lane];

    float4 acc = make_float4(0.f, 0.f, 0.f, 0.f);
    float den = 0.0f;

    int s0 = g_rowptr[i], s1 = g_rowptr[i + 1];
    int j = (s0 < s1) ? g_src[s0] : 0;
    for (int k = s0; k < s1; k++) {
        float4 xl = ((const float4*)g_xl)[j * 32 + lane];
        int jn = (k + 1 < s1) ? g_src[k + 1] : 0;   // prefetch next index

        float s = lrelu(xl.x + xr.x) * av.x
                + lrelu(xl.y + xr.y) * av.y
                + lrelu(xl.z + xr.z) * av.z
                + lrelu(xl.w + xr.w) * av.w;
        // reduce across the 8 lanes of this head
        s += __shfl_xor_sync(0xFFFFFFFFu, s, 1);
        s += __shfl_xor_sync(0xFFFFFFFFu, s, 2);
        s += __shfl_xor_sync(0xFFFFFFFFu, s, 4);

        float ex = __expf(s);
        den += ex;
        acc.x = fmaf(ex, xl.x, acc.x);
        acc.y = fmaf(ex, xl.y, acc.y);
        acc.z = fmaf(ex, xl.z, acc.z);
        acc.w = fmaf(ex, xl.w, acc.w);
        j = jn;
    }

    float inv = 1.0f / den;
    float4 bv = ((const float4*)bias)[lane];
    float4 o;
    o.x = fmaxf(fmaf(acc.x, inv, bv.x), 0.0f);
    o.y = fmaxf(fmaf(acc.y, inv, bv.y), 0.0f);
    o.z = fmaxf(fmaf(acc.z, inv, bv.z), 0.0f);
    o.w = fmaxf(fmaf(acc.w, inv, bv.w), 0.0f);

    // pooled max per graph; values >= 0 so int-compare atomicMax is order-correct
    int b = batch[i];
    int* pp = (int*)(pooled + b * HD + lane * 4);
    atomicMax(pp + 0, __float_as_int(o.x));
    atomicMax(pp + 1, __float_as_int(o.y));
    atomicMax(pp + 2, __float_as_int(o.z));
    atomicMax(pp + 3, __float_as_int(o.w));
}

// ---------------- launcher ---------------------------------------------------
extern "C" void kernel_launch(void* const* d_in, const int* in_sizes, int n_in,
                              void* d_out, int out_size) {
    const float* x    = (const float*)d_in[0];
    const int*   ei   = (const int*)d_in[1];
    const int*   batch= (const int*)d_in[2];
    const float* Wl   = (const float*)d_in[3];
    const float* bl   = (const float*)d_in[4];
    const float* Wr   = (const float*)d_in[5];
    const float* br   = (const float*)d_in[6];
    const float* att  = (const float*)d_in[7];
    const float* bias = (const float*)d_in[8];
    float* out = (float*)d_out;

    int n = in_sizes[2];          // nodes
    int E = in_sizes[1] / 2;      // edges
    const int* esrc = ei;
    const int* edst = ei + E;

    int initN = (n > out_size) ? n : out_size;
    init_kernel<<<(initN + 255) / 256, 256>>>(out, n, out_size);

    gemm_lr_kernel<<<(n + 15) / 16, 256>>>(x, Wl, bl, Wr, br, n);

    count_kernel<<<(E + 255) / 256, 256>>>(edst, E);
    scan_kernel<<<1, 1024>>>(n);
    fill_kernel<<<(E + n + 255) / 256, 256>>>(esrc, edst, E, n);

    gat_main_kernel<<<(n * 32 + 255) / 256, 256>>>(att, bias, batch, out, n);
}

// round 2
// speedup vs baseline: 4.8685x; 4.8685x over previous
#include <cuda_runtime.h>
#include <cuda_bf16.h>

#define NN 50000
#define EE 1600000
#define ETOT (EE + NN)
#define HD 128

typedef unsigned long long ull;

// ---------------- scratch (static device globals; no allocation) ------------
__device__ float g_xl[NN * HD];
__device__ float g_xr[NN * HD];
__device__ int   g_cnt[NN];
__device__ int   g_rowptr[NN + 1];
__device__ int   g_cursor[NN];
__device__ int   g_src[ETOT];

// ---------------- f32x2 packed-math helpers (FFMA2 on sm_103a) --------------
__device__ __forceinline__ ull pack2(float lo, float hi) {
    ull r; asm("mov.b64 %0, {%1, %2};" : "=l"(r) : "f"(lo), "f"(hi)); return r;
}
__device__ __forceinline__ float2 unpack2(ull v) {
    float2 r; asm("mov.b64 {%0, %1}, %2;" : "=f"(r.x), "=f"(r.y) : "l"(v)); return r;
}
__device__ __forceinline__ void fma2(ull& d, ull a, ull b) {
    asm("fma.rn.f32x2 %0, %1, %2, %0;" : "+l"(d) : "l"(a), "l"(b));
}

// ---------------- init: counts=1 (self loop), zero pooled output ------------
__global__ void init_kernel(float* __restrict__ out, int n, int out_elems) {
    int i = blockIdx.x * blockDim.x + threadIdx.x;
    if (i < n) g_cnt[i] = 1;                 // self-loop pre-count
    if (i < out_elems) out[i] = 0.0f;        // pooled init (matches isfinite->0 guard)
}

// ---------------- register-tiled dual GEMM ----------------------------------
// blockIdx.y selects (W_l -> g_xl) or (W_r -> g_xr).
// Block tile: 64 rows x 128 cols. 256 threads = 8 warps.
// Warp w owns rows [8w, 8w+8); lane owns cols [4*lane, 4*lane+4).
// A values are warp-uniform (broadcast LDS.64 over k-pairs); B via LDS.128.
// Accumulators are f32x2 packed over column pairs; math uses fma.rn.f32x2.
__global__ void __launch_bounds__(256, 2)
gemm_tiled_kernel(const float* __restrict__ x,
                  const float* __restrict__ Wl, const float* __restrict__ bl,
                  const float* __restrict__ Wr, const float* __restrict__ br,
                  int n) {
    extern __shared__ float sm[];
    float* xs = sm;                 // [64][128] row-major
    float* ws = sm + 64 * HD;       // [128][128] row-major

    const float* W    = blockIdx.y ? Wr : Wl;
    const float* bvec = blockIdx.y ? br : bl;
    float* out        = blockIdx.y ? g_xr : g_xl;

    int tid  = threadIdx.x;
    int lane = tid & 31;
    int w    = tid >> 5;
    int row0 = blockIdx.x * 64;

    // Load X tile (coalesced float4), zero-pad tail rows.
    for (int i4 = tid; i4 < 64 * 32; i4 += 256) {
        int r = i4 >> 5, c4 = i4 & 31;
        int row = row0 + r;
        float4 v = make_float4(0.f, 0.f, 0.f, 0.f);
        if (row < n) v = ((const float4*)x)[row * 32 + c4];
        ((float4*)xs)[i4] = v;
    }
    // Load W (straight coalesced copy).
    for (int i4 = tid; i4 < 128 * 32; i4 += 256) {
        ((float4*)ws)[i4] = ((const float4*)W)[i4];
    }
    __syncthreads();

    const float* arow = xs + (w * 8) * HD;
    ull accp[8][2];
#pragma unroll
    for (int r = 0; r < 8; r++) { accp[r][0] = 0ull; accp[r][1] = 0ull; }

#pragma unroll 4
    for (int k = 0; k < HD; k += 2) {
        float2 a01[8];
#pragma unroll
        for (int r = 0; r < 8; r++)
            a01[r] = *(const float2*)(arow + r * HD + k);       // warp-uniform broadcast

        float4 b0 = *(const float4*)(ws + k * HD + 4 * lane);       // k
        float4 b1 = *(const float4*)(ws + (k + 1) * HD + 4 * lane); // k+1
        ull bp00 = pack2(b0.x, b0.y), bp01 = pack2(b0.z, b0.w);
        ull bp10 = pack2(b1.x, b1.y), bp11 = pack2(b1.z, b1.w);

#pragma unroll
        for (int r = 0; r < 8; r++) {
            ull ad0 = pack2(a01[r].x, a01[r].x);
            fma2(accp[r][0], ad0, bp00);
            fma2(accp[r][1], ad0, bp01);
            ull ad1 = pack2(a01[r].y, a01[r].y);
            fma2(accp[r][0], ad1, bp10);
            fma2(accp[r][1], ad1, bp11);
        }
    }

    float4 bv = ((const float4*)bvec)[lane];
#pragma unroll
    for (int r = 0; r < 8; r++) {
        int row = row0 + w * 8 + r;
        if (row < n) {
            float2 p0 = unpack2(accp[r][0]);
            float2 p1 = unpack2(accp[r][1]);
            float4 o = make_float4(p0.x + bv.x, p0.y + bv.y, p1.x + bv.z, p1.y + bv.w);
            ((float4*)out)[row * 32 + lane] = o;
        }
    }
}

// ---------------- CSR build: count -> scan -> fill --------------------------
__global__ void count_kernel(const int* __restrict__ dst, int E) {
    int i = blockIdx.x * blockDim.x + threadIdx.x;
    if (i < E) atomicAdd(&g_cnt[dst[i]], 1);
}

// single block, smem-resident exclusive scan; all global traffic coalesced
__global__ void scan_kernel(int n) {
    extern __shared__ int buf[];       // n ints
    __shared__ int ssum[1024];
    int tid = threadIdx.x;

    for (int i = tid; i < n; i += 1024) buf[i] = g_cnt[i];
    __syncthreads();

    int chunk = (n + 1023) >> 10;
    int beg = min(tid * chunk, n), end = min(beg + chunk, n);
    int s = 0;
    for (int i = beg; i < end; i++) s += buf[i];     // stride-49 smem: conflict-free
    ssum[tid] = s;
    __syncthreads();
    for (int off = 1; off < 1024; off <<= 1) {
        int t = (tid >= off) ? ssum[tid - off] : 0;
        __syncthreads();
        ssum[tid] += t;
        __syncthreads();
    }
    int run = ssum[tid] - s;                          // exclusive base
    for (int i = beg; i < end; i++) { int v = buf[i]; buf[i] = run; run += v; }
    __syncthreads();
    for (int i = tid; i < n; i += 1024) { int v = buf[i]; g_rowptr[i] = v; g_cursor[i] = v; }
    if (tid == 1023) g_rowptr[n] = ssum[1023];
}

__global__ void fill_kernel(const int* __restrict__ src, const int* __restrict__ dst,
                            int E, int n) {
    int i = blockIdx.x * blockDim.x + threadIdx.x;
    if (i < E + n) {
        int s, d;
        if (i < E) { s = src[i]; d = dst[i]; }
        else       { s = i - E; d = s; }       // self loop
        int pos = atomicAdd(&g_cursor[d], 1);
        g_src[pos] = s;
    }
}

// ---------------- main fused GATv2 kernel: one warp per dst node ------------
__device__ __forceinline__ float lrelu(float v) { return (v > 0.0f) ? v : 0.2f * v; }

__global__ void gat_main_kernel(const float* __restrict__ att,
                                const float* __restrict__ bias,
                                const int* __restrict__ batch,
                                float* __restrict__ pooled, int n) {
    __shared__ int pbuf[HD];
    __shared__ int bmn, bmx;
    int tid = threadIdx.x;
    if (tid < HD) pbuf[tid] = 0;
    if (tid == 0) { bmn = 1 << 30; bmx = -1; }
    __syncthreads();

    int gw   = (blockIdx.x * blockDim.x + tid) >> 5;
    int lane = tid & 31;
    bool active = (gw < n);
    float4 o = make_float4(0.f, 0.f, 0.f, 0.f);
    int b = 0;

    if (active) {
        int i = gw;
        float4 xr = ((const float4*)g_xr)[i * 32 + lane];
        float4 av = ((const float4*)att)[lane];
        float4 acc = make_float4(0.f, 0.f, 0.f, 0.f);
        float den = 0.0f;

        int s0 = g_rowptr[i], s1 = g_rowptr[i + 1];
        int k = s0;
        for (; k + 2 <= s1; k += 2) {                 // 2-edge unroll: MLP x2
            int ja = __ldg(&g_src[k]);
            int jb = __ldg(&g_src[k + 1]);
            float4 xa = __ldg((const float4*)g_xl + ja * 32 + lane);
            float4 xb = __ldg((const float4*)g_xl + jb * 32 + lane);

            float sa = lrelu(xa.x + xr.x) * av.x + lrelu(xa.y + xr.y) * av.y
                     + lrelu(xa.z + xr.z) * av.z + lrelu(xa.w + xr.w) * av.w;
            float sb = lrelu(xb.x + xr.x) * av.x + lrelu(xb.y + xr.y) * av.y
                     + lrelu(xb.z + xr.z) * av.z + lrelu(xb.w + xr.w) * av.w;
            sa += __shfl_xor_sync(0xFFFFFFFFu, sa, 1);
            sb += __shfl_xor_sync(0xFFFFFFFFu, sb, 1);
            sa += __shfl_xor_sync(0xFFFFFFFFu, sa, 2);
            sb += __shfl_xor_sync(0xFFFFFFFFu, sb, 2);
            sa += __shfl_xor_sync(0xFFFFFFFFu, sa, 4);
            sb += __shfl_xor_sync(0xFFFFFFFFu, sb, 4);

            float ea = __expf(sa), eb = __expf(sb);
            den += ea + eb;
            acc.x = fmaf(ea, xa.x, fmaf(eb, xb.x, acc.x));
            acc.y = fmaf(ea, xa.y, fmaf(eb, xb.y, acc.y));
            acc.z = fmaf(ea, xa.z, fmaf(eb, xb.z, acc.z));
            acc.w = fmaf(ea, xa.w, fmaf(eb, xb.w, acc.w));
        }
        if (k < s1) {
            int j = __ldg(&g_src[k]);
            float4 xl = __ldg((const float4*)g_xl + j * 32 + lane);
            float s = lrelu(xl.x + xr.x) * av.x + lrelu(xl.y + xr.y) * av.y
                    + lrelu(xl.z + xr.z) * av.z + lrelu(xl.w + xr.w) * av.w;
            s += __shfl_xor_sync(0xFFFFFFFFu, s, 1);
            s += __shfl_xor_sync(0xFFFFFFFFu, s, 2);
            s += __shfl_xor_sync(0xFFFFFFFFu, s, 4);
            float ex = __expf(s);
            den += ex;
            acc.x = fmaf(ex, xl.x, acc.x);
            acc.y = fmaf(ex, xl.y, acc.y);
            acc.z = fmaf(ex, xl.z, acc.z);
            acc.w = fmaf(ex, xl.w, acc.w);
        }

        float inv = 1.0f / den;
        float4 bv = ((const float4*)bias)[lane];
        o.x = fmaxf(fmaf(acc.x, inv, bv.x), 0.0f);
        o.y = fmaxf(fmaf(acc.y, inv, bv.y), 0.0f);
        o.z = fmaxf(fmaf(acc.z, inv, bv.z), 0.0f);
        o.w = fmaxf(fmaf(acc.w, inv, bv.w), 0.0f);

        b = batch[i];
        if (lane == 0) { atomicMin(&bmn, b); atomicMax(&bmx, b); }
    }
    __syncthreads();

    if (bmn == bmx) {
        // batch-uniform block (common case: batch is sorted): smem pre-reduce
        if (active) {
            atomicMax(&pbuf[lane * 4 + 0], __float_as_int(o.x));
            atomicMax(&pbuf[lane * 4 + 1], __float_as_int(o.y));
            atomicMax(&pbuf[lane * 4 + 2], __float_as_int(o.z));
            atomicMax(&pbuf[lane * 4 + 3], __float_as_int(o.w));
        }
        __syncthreads();
        if (tid < HD && bmx >= 0)
            atomicMax((int*)pooled + bmx * HD + tid, pbuf[tid]);
    } else if (active) {
        int* pp = (int*)pooled + b * HD + lane * 4;
        atomicMax(pp + 0, __float_as_int(o.x));
        atomicMax(pp + 1, __float_as_int(o.y));
        atomicMax(pp + 2, __float_as_int(o.z));
        atomicMax(pp + 3, __float_as_int(o.w));
    }
}

// ---------------- launcher ---------------------------------------------------
extern "C" void kernel_launch(void* const* d_in, const int* in_sizes, int n_in,
                              void* d_out, int out_size) {
    const float* x    = (const float*)d_in[0];
    const int*   ei   = (const int*)d_in[1];
    const int*   batch= (const int*)d_in[2];
    const float* Wl   = (const float*)d_in[3];
    const float* bl   = (const float*)d_in[4];
    const float* Wr   = (const float*)d_in[5];
    const float* br   = (const float*)d_in[6];
    const float* att  = (const float*)d_in[7];
    const float* bias = (const float*)d_in[8];
    float* out = (float*)d_out;

    int n = in_sizes[2];          // nodes
    int E = in_sizes[1] / 2;      // edges
    const int* esrc = ei;
    const int* edst = ei + E;

    int gemm_smem = (64 * HD + HD * HD) * (int)sizeof(float);   // 96 KB
    int scan_smem = n * (int)sizeof(int);                        // ~200 KB
    cudaFuncSetAttribute(gemm_tiled_kernel,
                         cudaFuncAttributeMaxDynamicSharedMemorySize, gemm_smem);
    cudaFuncSetAttribute(scan_kernel,
                         cudaFuncAttributeMaxDynamicSharedMemorySize, scan_smem);

    int initN = (n > out_size) ? n : out_size;
    init_kernel<<<(initN + 255) / 256, 256>>>(out, n, out_size);

    dim3 ggrid((n + 63) / 64, 2);
    gemm_tiled_kernel<<<ggrid, 256, gemm_smem>>>(x, Wl, bl, Wr, br, n);

    count_kernel<<<(E + 255) / 256, 256>>>(edst, E);
    scan_kernel<<<1, 1024, scan_smem>>>(n);
    fill_kernel<<<(E + n + 255) / 256, 256>>>(esrc, edst, E, n);

    gat_main_kernel<<<(n * 32 + 255) / 256, 256>>>(att, bias, batch, out, n);
}

// round 3
// speedup vs baseline: 5.1682x; 1.0615x over previous
#include <cuda_runtime.h>
#include <cuda_bf16.h>

#define NN 50000
#define EE 1600000
#define ETOT (EE + NN)
#define HD 128

typedef unsigned long long ull;

// ---------------- scratch (static device globals; no allocation) ------------
__device__ float g_xl[NN * HD];
__device__ float g_xr[NN * HD];
__device__ int   g_cnt[NN];
__device__ int   g_rowptr[NN + 1];
__device__ int   g_cursor[NN];
__device__ int   g_src[ETOT];

// ---------------- f32x2 packed-math helpers (FFMA2 on sm_103a) --------------
__device__ __forceinline__ ull pack2(float lo, float hi) {
    ull r; asm("mov.b64 %0, {%1, %2};" : "=l"(r) : "f"(lo), "f"(hi)); return r;
}
__device__ __forceinline__ float2 unpack2(ull v) {
    float2 r; asm("mov.b64 {%0, %1}, %2;" : "=f"(r.x), "=f"(r.y) : "l"(v)); return r;
}
__device__ __forceinline__ void fma2(ull& d, ull a, ull b) {
    asm("fma.rn.f32x2 %0, %1, %2, %0;" : "+l"(d) : "l"(a), "l"(b));
}

// ---------------- small init kernels ----------------------------------------
__global__ void init_out_kernel(float* __restrict__ out, int out_elems) {
    int i = blockIdx.x * blockDim.x + threadIdx.x;
    if (i < out_elems) out[i] = 0.0f;        // pooled init (matches isfinite->0 guard)
}
__global__ void init_cnt_kernel(int n) {
    int i = blockIdx.x * blockDim.x + threadIdx.x;
    if (i < n) g_cnt[i] = 1;                 // self-loop pre-count
}

// ---------------- register-tiled dual GEMM ----------------------------------
// blockIdx.y selects (W_l -> g_xl) or (W_r -> g_xr).
// Block tile: 64 rows x 128 cols; 256 threads; warp w owns rows [8w,8w+8),
// lane owns cols [4*lane, 4*lane+4). Packed f32x2 accumulators (FFMA2).
__global__ void __launch_bounds__(256, 2)
gemm_tiled_kernel(const float* __restrict__ x,
                  const float* __restrict__ Wl, const float* __restrict__ bl,
                  const float* __restrict__ Wr, const float* __restrict__ br,
                  int n) {
    extern __shared__ float sm[];
    float* xs = sm;                 // [64][128]
    float* ws = sm + 64 * HD;       // [128][128]

    const float* W    = blockIdx.y ? Wr : Wl;
    const float* bvec = blockIdx.y ? br : bl;
    float* out        = blockIdx.y ? g_xr : g_xl;

    int tid  = threadIdx.x;
    int lane = tid & 31;
    int w    = tid >> 5;
    int row0 = blockIdx.x * 64;

    for (int i4 = tid; i4 < 64 * 32; i4 += 256) {
        int r = i4 >> 5;
        int row = row0 + r;
        float4 v = make_float4(0.f, 0.f, 0.f, 0.f);
        if (row < n) v = ((const float4*)x)[row * 32 + (i4 & 31)];
        ((float4*)xs)[i4] = v;
    }
    for (int i4 = tid; i4 < 128 * 32; i4 += 256)
        ((float4*)ws)[i4] = ((const float4*)W)[i4];
    __syncthreads();

    const float* arow = xs + (w * 8) * HD;
    ull accp[8][2];
#pragma unroll
    for (int r = 0; r < 8; r++) { accp[r][0] = 0ull; accp[r][1] = 0ull; }

#pragma unroll 4
    for (int k = 0; k < HD; k += 2) {
        float2 a01[8];
#pragma unroll
        for (int r = 0; r < 8; r++)
            a01[r] = *(const float2*)(arow + r * HD + k);   // warp-uniform broadcast

        float4 b0 = *(const float4*)(ws + k * HD + 4 * lane);
        float4 b1 = *(const float4*)(ws + (k + 1) * HD + 4 * lane);
        ull bp00 = pack2(b0.x, b0.y), bp01 = pack2(b0.z, b0.w);
        ull bp10 = pack2(b1.x, b1.y), bp11 = pack2(b1.z, b1.w);

#pragma unroll
        for (int r = 0; r < 8; r++) {
            ull ad0 = pack2(a01[r].x, a01[r].x);
            fma2(accp[r][0], ad0, bp00);
            fma2(accp[r][1], ad0, bp01);
            ull ad1 = pack2(a01[r].y, a01[r].y);
            fma2(accp[r][0], ad1, bp10);
            fma2(accp[r][1], ad1, bp11);
        }
    }

    float4 bv = ((const float4*)bvec)[lane];
#pragma unroll
    for (int r = 0; r < 8; r++) {
        int row = row0 + w * 8 + r;
        if (row < n) {
            float2 p0 = unpack2(accp[r][0]);
            float2 p1 = unpack2(accp[r][1]);
            ((float4*)out)[row * 32 + lane] =
                make_float4(p0.x + bv.x, p0.y + bv.y, p1.x + bv.z, p1.y + bv.w);
        }
    }
}

// ---------------- CSR build: count -> scan -> fill --------------------------
__global__ void count_kernel(const int* __restrict__ dst, int E) {
    int i = blockIdx.x * blockDim.x + threadIdx.x;
    if (i < E) atomicAdd(&g_cnt[dst[i]], 1);
}

__global__ void scan_kernel(int n) {
    extern __shared__ int buf[];
    __shared__ int ssum[1024];
    int tid = threadIdx.x;

    for (int i = tid; i < n; i += 1024) buf[i] = g_cnt[i];
    __syncthreads();

    int chunk = (n + 1023) >> 10;
    int beg = min(tid * chunk, n), end = min(beg + chunk, n);
    int s = 0;
    for (int i = beg; i < end; i++) s += buf[i];
    ssum[tid] = s;
    __syncthreads();
    for (int off = 1; off < 1024; off <<= 1) {
        int t = (tid >= off) ? ssum[tid - off] : 0;
        __syncthreads();
        ssum[tid] += t;
        __syncthreads();
    }
    int run = ssum[tid] - s;
    for (int i = beg; i < end; i++) { int v = buf[i]; buf[i] = run; run += v; }
    __syncthreads();
    for (int i = tid; i < n; i += 1024) { int v = buf[i]; g_rowptr[i] = v; g_cursor[i] = v; }
    if (tid == 1023) g_rowptr[n] = ssum[1023];
}

__global__ void fill_kernel(const int* __restrict__ src, const int* __restrict__ dst,
                            int E, int n) {
    int i = blockIdx.x * blockDim.x + threadIdx.x;
    if (i < E + n) {
        int s, d;
        if (i < E) { s = src[i]; d = dst[i]; }
        else       { s = i - E; d = s; }       // self loop
        int pos = atomicAdd(&g_cursor[d], 1);
        g_src[pos] = s;
    }
}

// ---------------- main fused GATv2 kernel: one warp per dst node ------------
__device__ __forceinline__ float lrelu(float v) { return (v > 0.0f) ? v : 0.2f * v; }

__global__ void gat_main_kernel(const float* __restrict__ att,
                                const float* __restrict__ bias,
                                const int* __restrict__ batch,
                                float* __restrict__ pooled, int n) {
    __shared__ int pbuf[HD];
    __shared__ int bmn, bmx;
    int tid = threadIdx.x;
    if (tid < HD) pbuf[tid] = 0;
    if (tid == 0) { bmn = 1 << 30; bmx = -1; }
    __syncthreads();

    int gw   = (blockIdx.x * blockDim.x + tid) >> 5;
    int lane = tid & 31;
    bool active = (gw < n);
    float4 o = make_float4(0.f, 0.f, 0.f, 0.f);
    int b = 0;

    if (active) {
        int i = gw;
        float4 xr = ((const float4*)g_xr)[i * 32 + lane];
        float4 av = ((const float4*)att)[lane];
        float4 acc = make_float4(0.f, 0.f, 0.f, 0.f);
        float den = 0.0f;

        int s0 = g_rowptr[i], s1 = g_rowptr[i + 1];
        int k = s0;
        // 4-edge unroll: 4 independent gathers in flight
        for (; k + 4 <= s1; k += 4) {
            int j[4];
#pragma unroll
            for (int u = 0; u < 4; u++) j[u] = __ldg(&g_src[k + u]);
            float4 xv[4];
#pragma unroll
            for (int u = 0; u < 4; u++)
                xv[u] = __ldg((const float4*)g_xl + j[u] * 32 + lane);

            float s[4];
#pragma unroll
            for (int u = 0; u < 4; u++)
                s[u] = lrelu(xv[u].x + xr.x) * av.x + lrelu(xv[u].y + xr.y) * av.y
                     + lrelu(xv[u].z + xr.z) * av.z + lrelu(xv[u].w + xr.w) * av.w;
#pragma unroll
            for (int u = 0; u < 4; u++) {
                s[u] += __shfl_xor_sync(0xFFFFFFFFu, s[u], 1);
                s[u] += __shfl_xor_sync(0xFFFFFFFFu, s[u], 2);
                s[u] += __shfl_xor_sync(0xFFFFFFFFu, s[u], 4);
            }
#pragma unroll
            for (int u = 0; u < 4; u++) {
                float ex = __expf(s[u]);
                den += ex;
                acc.x = fmaf(ex, xv[u].x, acc.x);
                acc.y = fmaf(ex, xv[u].y, acc.y);
                acc.z = fmaf(ex, xv[u].z, acc.z);
                acc.w = fmaf(ex, xv[u].w, acc.w);
            }
        }
        for (; k < s1; k++) {
            int j = __ldg(&g_src[k]);
            float4 xl = __ldg((const float4*)g_xl + j * 32 + lane);
            float s = lrelu(xl.x + xr.x) * av.x + lrelu(xl.y + xr.y) * av.y
                    + lrelu(xl.z + xr.z) * av.z + lrelu(xl.w + xr.w) * av.w;
            s += __shfl_xor_sync(0xFFFFFFFFu, s, 1);
            s += __shfl_xor_sync(0xFFFFFFFFu, s, 2);
            s += __shfl_xor_sync(0xFFFFFFFFu, s, 4);
            float ex = __expf(s);
            den += ex;
            acc.x = fmaf(ex, xl.x, acc.x);
            acc.y = fmaf(ex, xl.y, acc.y);
            acc.z = fmaf(ex, xl.z, acc.z);
            acc.w = fmaf(ex, xl.w, acc.w);
        }

        float inv = 1.0f / den;
        float4 bv = ((const float4*)bias)[lane];
        o.x = fmaxf(fmaf(acc.x, inv, bv.x), 0.0f);
        o.y = fmaxf(fmaf(acc.y, inv, bv.y), 0.0f);
        o.z = fmaxf(fmaf(acc.z, inv, bv.z), 0.0f);
        o.w = fmaxf(fmaf(acc.w, inv, bv.w), 0.0f);

        b = batch[i];
        if (lane == 0) { atomicMin(&bmn, b); atomicMax(&bmx, b); }
    }
    __syncthreads();

    if (bmn == bmx) {
        // batch-uniform block (batch is sorted): smem pre-reduce, 1 global atomic/ch
        if (active) {
            atomicMax(&pbuf[lane * 4 + 0], __float_as_int(o.x));
            atomicMax(&pbuf[lane * 4 + 1], __float_as_int(o.y));
            atomicMax(&pbuf[lane * 4 + 2], __float_as_int(o.z));
            atomicMax(&pbuf[lane * 4 + 3], __float_as_int(o.w));
        }
        __syncthreads();
        if (tid < HD && bmx >= 0)
            atomicMax((int*)pooled + bmx * HD + tid, pbuf[tid]);
    } else if (active) {
        int* pp = (int*)pooled + b * HD + lane * 4;
        atomicMax(pp + 0, __float_as_int(o.x));
        atomicMax(pp + 1, __float_as_int(o.y));
        atomicMax(pp + 2, __float_as_int(o.z));
        atomicMax(pp + 3, __float_as_int(o.w));
    }
}

// ---------------- launcher ---------------------------------------------------
extern "C" void kernel_launch(void* const* d_in, const int* in_sizes, int n_in,
                              void* d_out, int out_size) {
    const float* x    = (const float*)d_in[0];
    const int*   ei   = (const int*)d_in[1];
    const int*   batch= (const int*)d_in[2];
    const float* Wl   = (const float*)d_in[3];
    const float* bl   = (const float*)d_in[4];
    const float* Wr   = (const float*)d_in[5];
    const float* br   = (const float*)d_in[6];
    const float* att  = (const float*)d_in[7];
    const float* bias = (const float*)d_in[8];
    float* out = (float*)d_out;

    int n = in_sizes[2];          // nodes
    int E = in_sizes[1] / 2;      // edges
    const int* esrc = ei;
    const int* edst = ei + E;

    // side stream + fork/join events; created on the (uncaptured) correctness
    // call, reused identically on every call — device work is unchanged per call
    static cudaStream_t s2 = nullptr;
    static cudaEvent_t eFork = nullptr, eJoin = nullptr;
    if (s2 == nullptr) {
        cudaStreamCreateWithFlags(&s2, cudaStreamNonBlocking);
        cudaEventCreateWithFlags(&eFork, cudaEventDisableTiming);
        cudaEventCreateWithFlags(&eJoin, cudaEventDisableTiming);
    }

    int gemm_smem = (64 * HD + HD * HD) * (int)sizeof(float);   // 96 KB
    int scan_smem = n * (int)sizeof(int);                        // ~200 KB
    cudaFuncSetAttribute(gemm_tiled_kernel,
                         cudaFuncAttributeMaxDynamicSharedMemorySize, gemm_smem);
    cudaFuncSetAttribute(scan_kernel,
                         cudaFuncAttributeMaxDynamicSharedMemorySize, scan_smem);

    // fork: CSR build on s2, GEMM on the captured (default) stream
    cudaEventRecord(eFork, 0);
    cudaStreamWaitEvent(s2, eFork, 0);

    init_cnt_kernel<<<(n + 255) / 256, 256, 0, s2>>>(n);
    count_kernel<<<(E + 255) / 256, 256, 0, s2>>>(edst, E);
    scan_kernel<<<1, 1024, scan_smem, s2>>>(n);
    fill_kernel<<<(E + n + 255) / 256, 256, 0, s2>>>(esrc, edst, E, n);
    cudaEventRecord(eJoin, s2);

    init_out_kernel<<<(out_size + 255) / 256, 256>>>(out, out_size);
    dim3 ggrid((n + 63) / 64, 2);
    gemm_tiled_kernel<<<ggrid, 256, gemm_smem>>>(x, Wl, bl, Wr, br, n);

    // join, then fused GATv2 + pool
    cudaStreamWaitEvent(0, eJoin, 0);
    gat_main_kernel<<<(n * 32 + 255) / 256, 256>>>(att, bias, batch, out, n);
}

// round 4
// speedup vs baseline: 5.3960x; 1.0441x over previous
#include <cuda_runtime.h>
#include <cuda_fp16.h>
#include <cuda_bf16.h>

#define NN 50000
#define EE 1600000
#define ETOT (EE + NN)
#define HD 128

typedef unsigned long long ull;

// ---------------- scratch (static device globals; no allocation) ------------
__device__ __half g_xl16[NN * HD];    // fp16 mirror of xl (gathered per edge)
__device__ float  g_xr[NN * HD];
__device__ int    g_cnt[NN];
__device__ int    g_rowptr[NN + 1];
__device__ int    g_cursor[NN];
__device__ int    g_src[ETOT];

// ---------------- f32x2 packed-math helpers (FFMA2 on sm_103a) --------------
__device__ __forceinline__ ull pack2(float lo, float hi) {
    ull r; asm("mov.b64 %0, {%1, %2};" : "=l"(r) : "f"(lo), "f"(hi)); return r;
}
__device__ __forceinline__ float2 unpack2(ull v) {
    float2 r; asm("mov.b64 {%0, %1}, %2;" : "=f"(r.x), "=f"(r.y) : "l"(v)); return r;
}
__device__ __forceinline__ void fma2(ull& d, ull a, ull b) {
    asm("fma.rn.f32x2 %0, %1, %2, %0;" : "+l"(d) : "l"(a), "l"(b));
}

// ---------------- small init kernels ----------------------------------------
__global__ void init_out_kernel(float* __restrict__ out, int out_elems) {
    int i = blockIdx.x * blockDim.x + threadIdx.x;
    if (i < out_elems) out[i] = 0.0f;        // pooled init (matches isfinite->0 guard)
}
__global__ void init_cnt_kernel(int n) {
    int i = blockIdx.x * blockDim.x + threadIdx.x;
    if (i < n) g_cnt[i] = 1;                 // self-loop pre-count
}

// ---------------- register-tiled dual GEMM ----------------------------------
// blockIdx.y==0: W_l -> g_xl16 (fp16), blockIdx.y==1: W_r -> g_xr (fp32).
__global__ void __launch_bounds__(256, 2)
gemm_tiled_kernel(const float* __restrict__ x,
                  const float* __restrict__ Wl, const float* __restrict__ bl,
                  const float* __restrict__ Wr, const float* __restrict__ br,
                  int n) {
    extern __shared__ float sm[];
    float* xs = sm;                 // [64][128]
    float* ws = sm + 64 * HD;       // [128][128]

    const float* W    = blockIdx.y ? Wr : Wl;
    const float* bvec = blockIdx.y ? br : bl;

    int tid  = threadIdx.x;
    int lane = tid & 31;
    int w    = tid >> 5;
    int row0 = blockIdx.x * 64;

    for (int i4 = tid; i4 < 64 * 32; i4 += 256) {
        int r = i4 >> 5;
        int row = row0 + r;
        float4 v = make_float4(0.f, 0.f, 0.f, 0.f);
        if (row < n) v = ((const float4*)x)[row * 32 + (i4 & 31)];
        ((float4*)xs)[i4] = v;
    }
    for (int i4 = tid; i4 < 128 * 32; i4 += 256)
        ((float4*)ws)[i4] = ((const float4*)W)[i4];
    __syncthreads();

    const float* arow = xs + (w * 8) * HD;
    ull accp[8][2];
#pragma unroll
    for (int r = 0; r < 8; r++) { accp[r][0] = 0ull; accp[r][1] = 0ull; }

#pragma unroll 4
    for (int k = 0; k < HD; k += 2) {
        float2 a01[8];
#pragma unroll
        for (int r = 0; r < 8; r++)
            a01[r] = *(const float2*)(arow + r * HD + k);   // warp-uniform broadcast

        float4 b0 = *(const float4*)(ws + k * HD + 4 * lane);
        float4 b1 = *(const float4*)(ws + (k + 1) * HD + 4 * lane);
        ull bp00 = pack2(b0.x, b0.y), bp01 = pack2(b0.z, b0.w);
        ull bp10 = pack2(b1.x, b1.y), bp11 = pack2(b1.z, b1.w);

#pragma unroll
        for (int r = 0; r < 8; r++) {
            ull ad0 = pack2(a01[r].x, a01[r].x);
            fma2(accp[r][0], ad0, bp00);
            fma2(accp[r][1], ad0, bp01);
            ull ad1 = pack2(a01[r].y, a01[r].y);
            fma2(accp[r][0], ad1, bp10);
            fma2(accp[r][1], ad1, bp11);
        }
    }

    float4 bv = ((const float4*)bvec)[lane];
#pragma unroll
    for (int r = 0; r < 8; r++) {
        int row = row0 + w * 8 + r;
        if (row < n) {
            float2 p0 = unpack2(accp[r][0]);
            float2 p1 = unpack2(accp[r][1]);
            float4 o = make_float4(p0.x + bv.x, p0.y + bv.y, p1.x + bv.z, p1.y + bv.w);
            if (blockIdx.y) {
                ((float4*)g_xr)[row * 32 + lane] = o;
            } else {
                __half2 h01 = __floats2half2_rn(o.x, o.y);
                __half2 h23 = __floats2half2_rn(o.z, o.w);
                uint2 packed;
                packed.x = *(unsigned int*)&h01;
                packed.y = *(unsigned int*)&h23;
                ((uint2*)g_xl16)[row * 32 + lane] = packed;
            }
        }
    }
}

// ---------------- CSR build: count -> scan -> fill --------------------------
// 4 edges per thread (int4 loads) for MLP=4 on the latency-bound atomics
__global__ void count_kernel(const int* __restrict__ dst, int E) {
    int base = (blockIdx.x * blockDim.x + threadIdx.x) * 4;
    if (base + 3 < E) {
        int4 d = *(const int4*)(dst + base);
        atomicAdd(&g_cnt[d.x], 1);
        atomicAdd(&g_cnt[d.y], 1);
        atomicAdd(&g_cnt[d.z], 1);
        atomicAdd(&g_cnt[d.w], 1);
    } else {
        for (int i = base; i < E; i++) atomicAdd(&g_cnt[dst[i]], 1);
    }
}

__global__ void scan_kernel(int n) {
    extern __shared__ int buf[];
    __shared__ int ssum[1024];
    int tid = threadIdx.x;

    for (int i = tid; i < n; i += 1024) buf[i] = g_cnt[i];
    __syncthreads();

    int chunk = (n + 1023) >> 10;
    int beg = min(tid * chunk, n), end = min(beg + chunk, n);
    int s = 0;
    for (int i = beg; i < end; i++) s += buf[i];
    ssum[tid] = s;
    __syncthreads();
    for (int off = 1; off < 1024; off <<= 1) {
        int t = (tid >= off) ? ssum[tid - off] : 0;
        __syncthreads();
        ssum[tid] += t;
        __syncthreads();
    }
    int run = ssum[tid] - s;
    for (int i = beg; i < end; i++) { int v = buf[i]; buf[i] = run; run += v; }
    __syncthreads();
    for (int i = tid; i < n; i += 1024) { int v = buf[i]; g_rowptr[i] = v; g_cursor[i] = v; }
    if (tid == 1023) g_rowptr[n] = ssum[1023];
}

__global__ void fill_kernel(const int* __restrict__ src, const int* __restrict__ dst,
                            int E) {
    int base = (blockIdx.x * blockDim.x + threadIdx.x) * 4;
    if (base + 3 < E) {
        int4 s = *(const int4*)(src + base);
        int4 d = *(const int4*)(dst + base);
        int p0 = atomicAdd(&g_cursor[d.x], 1);
        int p1 = atomicAdd(&g_cursor[d.y], 1);
        int p2 = atomicAdd(&g_cursor[d.z], 1);
        int p3 = atomicAdd(&g_cursor[d.w], 1);
        g_src[p0] = s.x;
        g_src[p1] = s.y;
        g_src[p2] = s.z;
        g_src[p3] = s.w;
    } else {
        for (int i = base; i < E; i++) {
            int pos = atomicAdd(&g_cursor[dst[i]], 1);
            g_src[pos] = src[i];
        }
    }
}

__global__ void fill_loops_kernel(int n) {
    int i = blockIdx.x * blockDim.x + threadIdx.x;
    if (i < n) {
        int pos = atomicAdd(&g_cursor[i], 1);
        g_src[pos] = i;
    }
}

// ---------------- main fused GATv2 kernel: one warp per dst node ------------
__device__ __forceinline__ float lrelu(float v) { return (v > 0.0f) ? v : 0.2f * v; }

__device__ __forceinline__ float4 ld_xl16(int j, int lane) {
    uint2 raw = __ldg((const uint2*)g_xl16 + j * 32 + lane);
    __half2 h01 = *(__half2*)&raw.x;
    __half2 h23 = *(__half2*)&raw.y;
    float2 f01 = __half22float2(h01);
    float2 f23 = __half22float2(h23);
    return make_float4(f01.x, f01.y, f23.x, f23.y);
}

__global__ void gat_main_kernel(const float* __restrict__ att,
                                const float* __restrict__ bias,
                                const int* __restrict__ batch,
                                float* __restrict__ pooled, int n) {
    __shared__ int pbuf[HD];
    __shared__ int bmn, bmx;
    int tid = threadIdx.x;
    if (tid < HD) pbuf[tid] = 0;
    if (tid == 0) { bmn = 1 << 30; bmx = -1; }
    __syncthreads();

    int gw   = (blockIdx.x * blockDim.x + tid) >> 5;
    int lane = tid & 31;
    bool active = (gw < n);
    float4 o = make_float4(0.f, 0.f, 0.f, 0.f);
    int b = 0;

    if (active) {
        int i = gw;
        float4 xr = ((const float4*)g_xr)[i * 32 + lane];
        float4 av = ((const float4*)att)[lane];
        float4 acc = make_float4(0.f, 0.f, 0.f, 0.f);
        float den = 0.0f;

        int s0 = g_rowptr[i], s1 = g_rowptr[i + 1];
        int k = s0;
        for (; k + 4 <= s1; k += 4) {       // 4 independent gathers in flight
            int j[4];
#pragma unroll
            for (int u = 0; u < 4; u++) j[u] = __ldg(&g_src[k + u]);
            float4 xv[4];
#pragma unroll
            for (int u = 0; u < 4; u++) xv[u] = ld_xl16(j[u], lane);

            float s[4];
#pragma unroll
            for (int u = 0; u < 4; u++)
                s[u] = lrelu(xv[u].x + xr.x) * av.x + lrelu(xv[u].y + xr.y) * av.y
                     + lrelu(xv[u].z + xr.z) * av.z + lrelu(xv[u].w + xr.w) * av.w;
#pragma unroll
            for (int u = 0; u < 4; u++) {
                s[u] += __shfl_xor_sync(0xFFFFFFFFu, s[u], 1);
                s[u] += __shfl_xor_sync(0xFFFFFFFFu, s[u], 2);
                s[u] += __shfl_xor_sync(0xFFFFFFFFu, s[u], 4);
            }
#pragma unroll
            for (int u = 0; u < 4; u++) {
                float ex = __expf(s[u]);
                den += ex;
                acc.x = fmaf(ex, xv[u].x, acc.x);
                acc.y = fmaf(ex, xv[u].y, acc.y);
                acc.z = fmaf(ex, xv[u].z, acc.z);
                acc.w = fmaf(ex, xv[u].w, acc.w);
            }
        }
        for (; k < s1; k++) {
            int j = __ldg(&g_src[k]);
            float4 xl = ld_xl16(j, lane);
            float s = lrelu(xl.x + xr.x) * av.x + lrelu(xl.y + xr.y) * av.y
                    + lrelu(xl.z + xr.z) * av.z + lrelu(xl.w + xr.w) * av.w;
            s += __shfl_xor_sync(0xFFFFFFFFu, s, 1);
            s += __shfl_xor_sync(0xFFFFFFFFu, s, 2);
            s += __shfl_xor_sync(0xFFFFFFFFu, s, 4);
            float ex = __expf(s);
            den += ex;
            acc.x = fmaf(ex, xl.x, acc.x);
            acc.y = fmaf(ex, xl.y, acc.y);
            acc.z = fmaf(ex, xl.z, acc.z);
            acc.w = fmaf(ex, xl.w, acc.w);
        }

        float inv = 1.0f / den;
        float4 bv = ((const float4*)bias)[lane];
        o.x = fmaxf(fmaf(acc.x, inv, bv.x), 0.0f);
        o.y = fmaxf(fmaf(acc.y, inv, bv.y), 0.0f);
        o.z = fmaxf(fmaf(acc.z, inv, bv.z), 0.0f);
        o.w = fmaxf(fmaf(acc.w, inv, bv.w), 0.0f);

        b = batch[i];
        if (lane == 0) { atomicMin(&bmn, b); atomicMax(&bmx, b); }
    }
    __syncthreads();

    if (bmn == bmx) {
        if (active) {
            atomicMax(&pbuf[lane * 4 + 0], __float_as_int(o.x));
            atomicMax(&pbuf[lane * 4 + 1], __float_as_int(o.y));
            atomicMax(&pbuf[lane * 4 + 2], __float_as_int(o.z));
            atomicMax(&pbuf[lane * 4 + 3], __float_as_int(o.w));
        }
        __syncthreads();
        if (tid < HD && bmx >= 0)
            atomicMax((int*)pooled + bmx * HD + tid, pbuf[tid]);
    } else if (active) {
        int* pp = (int*)pooled + b * HD + lane * 4;
        atomicMax(pp + 0, __float_as_int(o.x));
        atomicMax(pp + 1, __float_as_int(o.y));
        atomicMax(pp + 2, __float_as_int(o.z));
        atomicMax(pp + 3, __float_as_int(o.w));
    }
}

// ---------------- launcher ---------------------------------------------------
extern "C" void kernel_launch(void* const* d_in, const int* in_sizes, int n_in,
                              void* d_out, int out_size) {
    const float* x    = (const float*)d_in[0];
    const int*   ei   = (const int*)d_in[1];
    const int*   batch= (const int*)d_in[2];
    const float* Wl   = (const float*)d_in[3];
    const float* bl   = (const float*)d_in[4];
    const float* Wr   = (const float*)d_in[5];
    const float* br   = (const float*)d_in[6];
    const float* att  = (const float*)d_in[7];
    const float* bias = (const float*)d_in[8];
    float* out = (float*)d_out;

    int n = in_sizes[2];          // nodes
    int E = in_sizes[1] / 2;      // edges
    const int* esrc = ei;
    const int* edst = ei + E;

    static cudaStream_t s2 = nullptr;
    static cudaEvent_t eFork = nullptr, eJoin = nullptr;
    if (s2 == nullptr) {
        cudaStreamCreateWithFlags(&s2, cudaStreamNonBlocking);
        cudaEventCreateWithFlags(&eFork, cudaEventDisableTiming);
        cudaEventCreateWithFlags(&eJoin, cudaEventDisableTiming);
    }

    int gemm_smem = (64 * HD + HD * HD) * (int)sizeof(float);   // 96 KB
    int scan_smem = n * (int)sizeof(int);                        // ~200 KB
    cudaFuncSetAttribute(gemm_tiled_kernel,
                         cudaFuncAttributeMaxDynamicSharedMemorySize, gemm_smem);
    cudaFuncSetAttribute(scan_kernel,
                         cudaFuncAttributeMaxDynamicSharedMemorySize, scan_smem);

    // fork: CSR build on s2, GEMM on the captured (default) stream
    cudaEventRecord(eFork, 0);
    cudaStreamWaitEvent(s2, eFork, 0);

    int e4 = (E + 3) / 4;
    init_cnt_kernel<<<(n + 255) / 256, 256, 0, s2>>>(n);
    count_kernel<<<(e4 + 255) / 256, 256, 0, s2>>>(edst, E);
    scan_kernel<<<1, 1024, scan_smem, s2>>>(n);
    fill_kernel<<<(e4 + 255) / 256, 256, 0, s2>>>(esrc, edst, E);
    fill_loops_kernel<<<(n + 255) / 256, 256, 0, s2>>>(n);
    cudaEventRecord(eJoin, s2);

    init_out_kernel<<<(out_size + 255) / 256, 256>>>(out, out_size);
    dim3 ggrid((n + 63) / 64, 2);
    gemm_tiled_kernel<<<ggrid, 256, gemm_smem>>>(x, Wl, bl, Wr, br, n);

    // join, then fused GATv2 + pool
    cudaStreamWaitEvent(0, eJoin, 0);
    gat_main_kernel<<<(n * 32 + 255) / 256, 256>>>(att, bias, batch, out, n);
}